// round 1
// baseline (speedup 1.0000x reference)
#include <cuda_runtime.h>
#include <math.h>

#define BATCH   512
#define NSTEPS  20000
#define NTUM    64
#define NCHUNK  125      // chunks per batch
#define CS      160      // steps per chunk
#define NGRP    5        // 32-step groups per chunk
#define WARPS_TOTAL (BATCH * NCHUNK)        // 64000
#define PASS_BLOCKS (WARPS_TOTAL / 8)       // 8000 blocks of 8 warps

// ---------------- scratch (no allocations allowed) ----------------
__device__ float    g_e0s  [BATCH * (NTUM + 1) * 3];          // frames per batch
__device__ unsigned g_ball [BATCH * NCHUNK * NGRP * 3];       // ballot words
__device__ unsigned g_cinfo[NCHUNK * BATCH];                  // exitA|exitB<<2|cntA<<4|cntB<<16
__device__ unsigned g_entry[NCHUNK * BATCH];                  // z_in | C_in<<1
__device__ float    g_vsum [NCHUNK * BATCH * 3];              // chunk velocity sums
__device__ float    g_off  [NCHUNK * BATCH * 3];              // chunk offsets

// ---------------- small vector helpers (match fp32 reference math) ------
struct F3 { float x, y, z; };
__device__ __forceinline__ F3 mk3(float x, float y, float z) { F3 r{x, y, z}; return r; }
__device__ __forceinline__ float dot3(F3 a, F3 b) { return a.x * b.x + a.y * b.y + a.z * b.z; }
__device__ __forceinline__ F3 cross3(F3 a, F3 b) {
    return mk3(a.y * b.z - a.z * b.y, a.z * b.x - a.x * b.z, a.x * b.y - a.y * b.x);
}
__device__ __forceinline__ F3 nrm3(F3 v) {
    float n = sqrtf(v.x * v.x + v.y * v.y + v.z * v.z);
    return mk3(v.x / n, v.y / n, v.z / n);
}
__device__ __forceinline__ F3 ortho3(F3 v, F3 u) {
    float k = dot3(v, u) / dot3(u, u);
    return mk3(v.x - k * u.x, v.y - k * u.y, v.z - k * u.z);
}
// R v with R = c I + s [u]_x + (1-c) u u^T
__device__ __forceinline__ F3 rodApply(F3 u, float c, float s, F3 v) {
    F3 cv = cross3(u, v);
    float d = dot3(u, v);
    float oc = 1.0f - c;
    return mk3(c * v.x + s * cv.x + oc * d * u.x,
               c * v.y + s * cv.y + oc * d * u.y,
               c * v.z + s * cv.z + oc * d * u.z);
}
__device__ __forceinline__ float cauchy_angle(float u, float sig) {
    float a = sig * tanf((float)M_PI * (u - 0.5f));   // mu = 0
    if (!isfinite(a)) a = 0.0f;
    return fmodf(a, (float)M_PI);
}

// ---------------- frame chain (64 sequential rotations per batch) -------
__device__ void frames_work(int b, const float* __restrict__ v0,
                            const float* __restrict__ v1,
                            const float* __restrict__ up,
                            const float* __restrict__ un) {
    F3 a = mk3(v0[b * 3 + 0], v0[b * 3 + 1], v0[b * 3 + 2]);
    F3 c = mk3(v1[b * 3 + 0], v1[b * 3 + 1], v1[b * 3 + 2]);
    F3 e0 = nrm3(a);
    F3 e1 = nrm3(ortho3(c, e0));
    F3 e2 = nrm3(cross3(e0, e1));
    float* out = &g_e0s[b * (NTUM + 1) * 3];
    out[0] = e0.x; out[1] = e0.y; out[2] = e0.z;
    for (int i = 0; i < NTUM; ++i) {
        float ap = cauchy_angle(up[b * NTUM + i], 0.1f);
        float an = cauchy_angle(un[b * NTUM + i], 0.5f);
        // planar: rotate e0, e1 about e2
        float cp = cosf(ap), sp = sinf(ap);
        F3 n0 = nrm3(rodApply(e2, cp, sp, e0));
        F3 n1 = nrm3(rodApply(e2, cp, sp, e1));
        e0 = n0;
        e1 = nrm3(ortho3(n1, e0));
        e2 = nrm3(cross3(e0, e1));
        // nonplanar: rotate e0 about (current) e1
        float cn = cosf(an), sn = sinf(an);
        e0 = nrm3(rodApply(e1, cn, sn, e0));
        e1 = nrm3(ortho3(e1, e0));
        e2 = nrm3(cross3(e0, e1));
        out[(i + 1) * 3 + 0] = e0.x;
        out[(i + 1) * 3 + 1] = e0.y;
        out[(i + 1) * 3 + 2] = e0.z;
    }
}

// ---------------- affine GF(2) prefix over 32 steps ----------------------
// z_t = p_t * z_{t-1} XOR q_t, bit t = step t (LSB earliest).
// p = a ^ b, q = b with a = [next-from-0 == 0], b = [next-from-{1,2} == 0].
__device__ __forceinline__ unsigned affineZ(unsigned wA1, unsigned wA2,
                                            unsigned wB0, unsigned zin) {
    unsigned a = ~(wA1 | wA2);
    unsigned P = a ^ wB0;
    unsigned Q = wB0;
#pragma unroll
    for (int k = 1; k < 32; k <<= 1) {
        Q = Q ^ (P & (Q << k));
        P = P & ((P << k) | ((1u << k) - 1u));
    }
    return Q ^ (zin ? P : 0u);
}

// ---------------- pass 1: ballots + per-chunk map/counts (+ fused frames)
__global__ void __launch_bounds__(256) k_pass1(const float* __restrict__ r0,
                                               const float* __restrict__ r1,
                                               const float* __restrict__ v0,
                                               const float* __restrict__ v1,
                                               const float* __restrict__ up,
                                               const float* __restrict__ un) {
    if (blockIdx.x >= PASS_BLOCKS) {
        int b = (blockIdx.x - PASS_BLOCKS) * blockDim.x + threadIdx.x;
        if (b < BATCH) frames_work(b, v0, v1, up, un);
        return;
    }
    const float R01 = 1e-3f, R10 = 1e-3f;
    const float TH = (float)(1.0 - 1e-3);   // matches python 1.0 - RATE_02 cast to f32

    int w = blockIdx.x * 8 + (threadIdx.x >> 5);
    int lane = threadIdx.x & 31;
    int b = w / NCHUNK;
    int chunk = w - b * NCHUNK;
    int base = b * NSTEPS + chunk * CS;

    unsigned zA = 1u, zB = 0u;      // path A: entry state 0; path B: entry state 1/2
    int cntA = 0, cntB = 0;
    unsigned lastZA = 0, lastZB = 0, lastS2A = 0, lastS2B = 0;
#pragma unroll
    for (int g = 0; g < NGRP; ++g) {
        float a0 = r0[base + g * 32 + lane];
        float a1 = r1[base + g * 32 + lane];
        unsigned wA1 = __ballot_sync(0xffffffffu, a0 < R01);
        unsigned wA2 = __ballot_sync(0xffffffffu, a0 > TH);
        unsigned wB0 = __ballot_sync(0xffffffffu, a1 < R10);
        if (lane < 3) {
            unsigned val = (lane == 0) ? wA1 : (lane == 1 ? wA2 : wB0);
            g_ball[((b * NCHUNK + chunk) * NGRP + g) * 3 + lane] = val;
        }
        unsigned ZA = affineZ(wA1, wA2, wB0, zA);
        unsigned ZB = affineZ(wA1, wA2, wB0, zB);
        unsigned ZpA = (ZA << 1) | zA;
        unsigned ZpB = (ZB << 1) | zB;
        unsigned S2A = ZpA & wA2;
        unsigned S2B = ZpB & wA2;
        if (chunk == 0 && g == 0) { S2A &= ~1u; S2B &= ~1u; }   // step 0 never a tumble
        cntA += __popc(S2A);
        cntB += __popc(S2B);
        zA = ZA >> 31;
        zB = ZB >> 31;
        lastZA = ZA; lastZB = ZB; lastS2A = S2A; lastS2B = S2B;
    }
    unsigned exA = ((lastZA >> 31) & 1u) ? 0u : (((lastS2A >> 31) & 1u) ? 2u : 1u);
    unsigned exB = ((lastZB >> 31) & 1u) ? 0u : (((lastS2B >> 31) & 1u) ? 2u : 1u);
    if (lane == 0)
        g_cinfo[chunk * BATCH + b] =
            exA | (exB << 2) | ((unsigned)cntA << 4) | ((unsigned)cntB << 16);
}

// ---------------- scan A: per-batch chunk entry state + tumble prefix ----
__global__ void __launch_bounds__(256) k_scanA() {
    int b = blockIdx.x * blockDim.x + threadIdx.x;
    if (b >= BATCH) return;
    int s = 0;
    unsigned C = 0;
#pragma unroll 5
    for (int j = 0; j < NCHUNK; ++j) {
        unsigned z = (s == 0) ? 1u : 0u;
        g_entry[j * BATCH + b] = z | (C << 1);
        unsigned info = g_cinfo[j * BATCH + b];
        C += z ? ((info >> 4) & 0xFFFu) : ((info >> 16) & 0xFFFFu);
        s = (int)(z ? (info & 3u) : ((info >> 2) & 3u));
    }
}

// ---------------- pass 2: per-chunk velocity sums -------------------------
__global__ void __launch_bounds__(256) k_pass2(const float* __restrict__ x0) {
    int w = blockIdx.x * 8 + (threadIdx.x >> 5);
    int lane = threadIdx.x & 31;
    int b = w / NCHUNK;
    int chunk = w - b * NCHUNK;

    unsigned e = g_entry[chunk * BATCH + b];
    unsigned z = e & 1u;
    int Cin = (int)(e >> 1);
    int sofar = 0;
    unsigned lemask = 0xffffffffu >> (31 - lane);
    const float* e0s = &g_e0s[b * (NTUM + 1) * 3];
    float ax = 0.f, ay = 0.f, az = 0.f;
#pragma unroll
    for (int g = 0; g < NGRP; ++g) {
        const unsigned* p = &g_ball[((b * NCHUNK + chunk) * NGRP + g) * 3];
        unsigned wA1 = p[0], wA2 = p[1], wB0 = p[2];
        unsigned Z = affineZ(wA1, wA2, wB0, z);
        unsigned Zp = (Z << 1) | z;
        unsigned S2 = Zp & wA2;
        unsigned S1 = (Zp & wA1) | (~Zp & ~wB0);
        if (chunk == 0 && g == 0) S2 &= ~1u;
        int c = Cin + sofar + __popc(S2 & lemask);
        sofar += __popc(S2);
        z = Z >> 31;
        bool tum = (S2 >> lane) & 1u;
        if (chunk == 0 && g == 0 && lane == 0) {
            ax += x0[b * 3 + 0]; ay += x0[b * 3 + 1]; az += x0[b * 3 + 2];
        } else if (!tum) {
            float sp = ((S1 >> lane) & 1u) ? 5e-3f : 1e-3f;
            int idx = c - 1;
            idx = idx < 0 ? 0 : (idx > NTUM ? NTUM : idx);
            ax += sp * e0s[idx * 3 + 0];
            ay += sp * e0s[idx * 3 + 1];
            az += sp * e0s[idx * 3 + 2];
        }
    }
#pragma unroll
    for (int o = 16; o; o >>= 1) {
        ax += __shfl_xor_sync(0xffffffffu, ax, o);
        ay += __shfl_xor_sync(0xffffffffu, ay, o);
        az += __shfl_xor_sync(0xffffffffu, az, o);
    }
    if (lane == 0) {
        g_vsum[(chunk * BATCH + b) * 3 + 0] = ax;
        g_vsum[(chunk * BATCH + b) * 3 + 1] = ay;
        g_vsum[(chunk * BATCH + b) * 3 + 2] = az;
    }
}

// ---------------- scan B: chunk offsets -----------------------------------
__global__ void __launch_bounds__(256) k_scanB() {
    int b = blockIdx.x * blockDim.x + threadIdx.x;
    if (b >= BATCH) return;
    double rx = 0.0, ry = 0.0, rz = 0.0;
#pragma unroll 5
    for (int j = 0; j < NCHUNK; ++j) {
        g_off[(j * BATCH + b) * 3 + 0] = (float)rx;
        g_off[(j * BATCH + b) * 3 + 1] = (float)ry;
        g_off[(j * BATCH + b) * 3 + 2] = (float)rz;
        rx += (double)g_vsum[(j * BATCH + b) * 3 + 0];
        ry += (double)g_vsum[(j * BATCH + b) * 3 + 1];
        rz += (double)g_vsum[(j * BATCH + b) * 3 + 2];
    }
}

// ---------------- pass 3: write trajectory --------------------------------
__global__ void __launch_bounds__(256) k_pass3(const float* __restrict__ x0,
                                               float* __restrict__ out) {
    int w = blockIdx.x * 8 + (threadIdx.x >> 5);
    int lane = threadIdx.x & 31;
    int b = w / NCHUNK;
    int chunk = w - b * NCHUNK;

    unsigned e = g_entry[chunk * BATCH + b];
    unsigned z = e & 1u;
    int Cin = (int)(e >> 1);
    int sofar = 0;
    unsigned lemask = 0xffffffffu >> (31 - lane);
    const float* e0s = &g_e0s[b * (NTUM + 1) * 3];
    float cx = g_off[(chunk * BATCH + b) * 3 + 0];
    float cy = g_off[(chunk * BATCH + b) * 3 + 1];
    float cz = g_off[(chunk * BATCH + b) * 3 + 2];
    int base = b * NSTEPS + chunk * CS;
#pragma unroll
    for (int g = 0; g < NGRP; ++g) {
        const unsigned* p = &g_ball[((b * NCHUNK + chunk) * NGRP + g) * 3];
        unsigned wA1 = p[0], wA2 = p[1], wB0 = p[2];
        unsigned Z = affineZ(wA1, wA2, wB0, z);
        unsigned Zp = (Z << 1) | z;
        unsigned S2 = Zp & wA2;
        unsigned S1 = (Zp & wA1) | (~Zp & ~wB0);
        if (chunk == 0 && g == 0) S2 &= ~1u;
        int c = Cin + sofar + __popc(S2 & lemask);
        sofar += __popc(S2);
        z = Z >> 31;
        float vx, vy, vz;
        bool tum = (S2 >> lane) & 1u;
        if (chunk == 0 && g == 0 && lane == 0) {
            vx = x0[b * 3 + 0]; vy = x0[b * 3 + 1]; vz = x0[b * 3 + 2];
        } else if (tum) {
            vx = vy = vz = 0.f;
        } else {
            float sp = ((S1 >> lane) & 1u) ? 5e-3f : 1e-3f;
            int idx = c - 1;
            idx = idx < 0 ? 0 : (idx > NTUM ? NTUM : idx);
            vx = sp * e0s[idx * 3 + 0];
            vy = sp * e0s[idx * 3 + 1];
            vz = sp * e0s[idx * 3 + 2];
        }
        // inclusive warp scan of float3
#pragma unroll
        for (int o = 1; o < 32; o <<= 1) {
            float tx = __shfl_up_sync(0xffffffffu, vx, o);
            float ty = __shfl_up_sync(0xffffffffu, vy, o);
            float tz = __shfl_up_sync(0xffffffffu, vz, o);
            if (lane >= o) { vx += tx; vy += ty; vz += tz; }
        }
        int t3 = (base + g * 32 + lane) * 3;
        out[t3 + 0] = cx + vx;
        out[t3 + 1] = cy + vy;
        out[t3 + 2] = cz + vz;
        cx += __shfl_sync(0xffffffffu, vx, 31);
        cy += __shfl_sync(0xffffffffu, vy, 31);
        cz += __shfl_sync(0xffffffffu, vz, 31);
    }
}

// ---------------- launch ----------------------------------------------------
extern "C" void kernel_launch(void* const* d_in, const int* in_sizes, int n_in,
                              void* d_out, int out_size) {
    const float* x0 = (const float*)d_in[0];
    const float* v0 = (const float*)d_in[1];
    const float* v1 = (const float*)d_in[2];
    const float* r0 = (const float*)d_in[3];
    const float* r1 = (const float*)d_in[4];
    const float* up = (const float*)d_in[5];
    const float* un = (const float*)d_in[6];
    float* X = (float*)d_out;

    k_pass1<<<PASS_BLOCKS + 2, 256>>>(r0, r1, v0, v1, up, un);
    k_scanA<<<2, 256>>>();
    k_pass2<<<PASS_BLOCKS, 256>>>(x0);
    k_scanB<<<2, 256>>>();
    k_pass3<<<PASS_BLOCKS, 256>>>(x0, X);
}

// round 2
// speedup vs baseline: 2.5287x; 2.5287x over previous
#include <cuda_runtime.h>
#include <math.h>

#define BATCH   512
#define NSTEPS  20000
#define NTUM    64
#define NCHUNK  125      // chunks per batch
#define CS      160      // steps per chunk
#define NGRP    5        // 32-step groups per chunk
#define NWW     8        // worker warps per block
#define THREADS 288      // 8 worker warps + 1 frame warp

// ---------------- small vector helpers ----------------
struct F3 { float x, y, z; };
__device__ __forceinline__ F3 mk3(float x, float y, float z) { F3 r{x, y, z}; return r; }
__device__ __forceinline__ float dot3(F3 a, F3 b) { return a.x * b.x + a.y * b.y + a.z * b.z; }
__device__ __forceinline__ F3 cross3(F3 a, F3 b) {
    return mk3(a.y * b.z - a.z * b.y, a.z * b.x - a.x * b.z, a.x * b.y - a.y * b.x);
}
__device__ __forceinline__ F3 nrm3(F3 v) {
    float r = rsqrtf(v.x * v.x + v.y * v.y + v.z * v.z);
    return mk3(v.x * r, v.y * r, v.z * r);
}
__device__ __forceinline__ F3 ortho3(F3 v, F3 u) {
    float k = __fdividef(dot3(v, u), dot3(u, u));
    return mk3(v.x - k * u.x, v.y - k * u.y, v.z - k * u.z);
}
__device__ __forceinline__ F3 rodApply(F3 u, float c, float s, F3 v) {
    F3 cv = cross3(u, v);
    float d = dot3(u, v);
    float oc = 1.0f - c;
    return mk3(c * v.x + s * cv.x + oc * d * u.x,
               c * v.y + s * cv.y + oc * d * u.y,
               c * v.z + s * cv.z + oc * d * u.z);
}
__device__ __forceinline__ float cauchy_angle(float u, float sig) {
    float a = sig * tanf((float)M_PI * (u - 0.5f));   // mu = 0
    if (!isfinite(a)) a = 0.0f;
    return fmodf(a, (float)M_PI);
}

// ---------------- affine GF(2) prefix over 32 steps ----------------------
// z_t = p_t * z_{t-1} XOR q_t, bit t = step t (LSB earliest).
__device__ __forceinline__ unsigned affineZ(unsigned wA1, unsigned wA2,
                                            unsigned wB0, unsigned zin) {
    unsigned a = ~(wA1 | wA2);
    unsigned P = a ^ wB0;
    unsigned Q = wB0;
#pragma unroll
    for (int k = 1; k < 32; k <<= 1) {
        Q = Q ^ (P & (Q << k));
        P = P & ((P << k) | ((1u << k) - 1u));
    }
    return Q ^ (zin ? P : 0u);
}

// ============================================================================
// Single fused kernel: one block per batch.
// ============================================================================
__global__ void __launch_bounds__(THREADS, 4)
k_fused(const float* __restrict__ x0, const float* __restrict__ v0,
        const float* __restrict__ v1, const float* __restrict__ r0,
        const float* __restrict__ r1, const float* __restrict__ up,
        const float* __restrict__ un, float* __restrict__ out) {
    __shared__ unsigned s_ball[NCHUNK * NGRP * 3];   // 7.5 KB ballots
    __shared__ unsigned s_cinfo[NCHUNK];
    __shared__ unsigned s_entry[NCHUNK];
    __shared__ float    s_coffx[NCHUNK], s_coffy[NCHUNK], s_coffz[NCHUNK];
    __shared__ float    s_wtot[NWW][3];
    __shared__ float    s_wbase[NWW][3];
    __shared__ float    s_e0s[(NTUM + 1) * 3];
    __shared__ float    s_cp[NTUM], s_sp[NTUM], s_cn[NTUM], s_sn[NTUM];

    const int b    = blockIdx.x;
    const int tid  = threadIdx.x;
    const int w    = tid >> 5;
    const int lane = tid & 31;

    const float R01 = 1e-3f, R10 = 1e-3f;
    const float TH  = (float)(1.0 - 1e-3);
    const unsigned lemask = 0xffffffffu >> (31 - lane);

    // chunk range for worker warp w (warps 0-4: 16 chunks, warps 5-7: 15)
    int cs = 0, ce = 0;
    if (w < NWW) {
        cs = (w < 5) ? w * 16 : 80 + (w - 5) * 15;
        ce = cs + ((w < 5) ? 16 : 15);
    }

    // ---------------- phase 1: ballots + per-chunk info / frame chain -----
    if (w == NWW) {
        // lane-parallel trig precompute (input-only)
        for (int i = lane; i < NTUM; i += 32) {
            float ap = cauchy_angle(up[b * NTUM + i], 0.1f);
            float an = cauchy_angle(un[b * NTUM + i], 0.5f);
            s_cp[i] = cosf(ap); s_sp[i] = sinf(ap);
            s_cn[i] = cosf(an); s_sn[i] = sinf(an);
        }
        __syncwarp();
        if (lane == 0) {
            F3 a = mk3(v0[b * 3 + 0], v0[b * 3 + 1], v0[b * 3 + 2]);
            F3 c = mk3(v1[b * 3 + 0], v1[b * 3 + 1], v1[b * 3 + 2]);
            F3 e0 = nrm3(a);
            F3 e1 = nrm3(ortho3(c, e0));
            F3 e2 = nrm3(cross3(e0, e1));
            s_e0s[0] = e0.x; s_e0s[1] = e0.y; s_e0s[2] = e0.z;
            for (int i = 0; i < NTUM; ++i) {
                float cp = s_cp[i], sp = s_sp[i];
                F3 n0 = nrm3(rodApply(e2, cp, sp, e0));
                F3 n1 = nrm3(rodApply(e2, cp, sp, e1));
                e0 = n0;
                e1 = nrm3(ortho3(n1, e0));
                e2 = nrm3(cross3(e0, e1));
                float cn = s_cn[i], sn = s_sn[i];
                e0 = nrm3(rodApply(e1, cn, sn, e0));
                e1 = nrm3(ortho3(e1, e0));
                e2 = nrm3(cross3(e0, e1));
                s_e0s[(i + 1) * 3 + 0] = e0.x;
                s_e0s[(i + 1) * 3 + 1] = e0.y;
                s_e0s[(i + 1) * 3 + 2] = e0.z;
            }
        }
    } else {
        for (int ck = cs; ck < ce; ++ck) {
            int base = b * NSTEPS + ck * CS;
            unsigned zA = 1u, zB = 0u;
            int cntA = 0, cntB = 0;
            unsigned lastZA = 0, lastZB = 0, lastS2A = 0, lastS2B = 0;
#pragma unroll
            for (int g = 0; g < NGRP; ++g) {
                float a0 = r0[base + g * 32 + lane];
                float a1 = r1[base + g * 32 + lane];
                unsigned wA1 = __ballot_sync(0xffffffffu, a0 < R01);
                unsigned wA2 = __ballot_sync(0xffffffffu, a0 > TH);
                unsigned wB0 = __ballot_sync(0xffffffffu, a1 < R10);
                if (lane < 3) {
                    unsigned val = (lane == 0) ? wA1 : (lane == 1 ? wA2 : wB0);
                    s_ball[(ck * NGRP + g) * 3 + lane] = val;
                }
                unsigned ZA = affineZ(wA1, wA2, wB0, zA);
                unsigned ZB = affineZ(wA1, wA2, wB0, zB);
                unsigned ZpA = (ZA << 1) | zA;
                unsigned ZpB = (ZB << 1) | zB;
                unsigned S2A = ZpA & wA2;
                unsigned S2B = ZpB & wA2;
                if (ck == 0 && g == 0) { S2A &= ~1u; S2B &= ~1u; }
                cntA += __popc(S2A);
                cntB += __popc(S2B);
                zA = ZA >> 31;
                zB = ZB >> 31;
                lastZA = ZA; lastZB = ZB; lastS2A = S2A; lastS2B = S2B;
            }
            unsigned exA = ((lastZA >> 31) & 1u) ? 0u : (((lastS2A >> 31) & 1u) ? 2u : 1u);
            unsigned exB = ((lastZB >> 31) & 1u) ? 0u : (((lastS2B >> 31) & 1u) ? 2u : 1u);
            if (lane == 0)
                s_cinfo[ck] = exA | (exB << 2) |
                              ((unsigned)cntA << 4) | ((unsigned)cntB << 16);
        }
    }
    __syncthreads();

    // ---------------- scan A: chunk entry state + tumble prefix -----------
    if (tid == 0) {
        int s = 0;
        unsigned C = 0;
        for (int j = 0; j < NCHUNK; ++j) {
            unsigned z = (s == 0) ? 1u : 0u;
            s_entry[j] = z | (C << 1);
            unsigned info = s_cinfo[j];
            C += z ? ((info >> 4) & 0xFFFu) : ((info >> 16) & 0xFFFFu);
            s = (int)(z ? (info & 3u) : ((info >> 2) & 3u));
        }
    }
    __syncthreads();

    // ---------------- phase 3: per-chunk velocity sums + warp prefix ------
    if (w < NWW) {
        float rx = 0.f, ry = 0.f, rz = 0.f;
        for (int ck = cs; ck < ce; ++ck) {
            unsigned e = s_entry[ck];
            unsigned z = e & 1u;
            int Cin = (int)(e >> 1);
            int sofar = 0;
            float ax = 0.f, ay = 0.f, az = 0.f;
#pragma unroll
            for (int g = 0; g < NGRP; ++g) {
                const unsigned* p = &s_ball[(ck * NGRP + g) * 3];
                unsigned wA1 = p[0], wA2 = p[1], wB0 = p[2];
                unsigned Z = affineZ(wA1, wA2, wB0, z);
                unsigned Zp = (Z << 1) | z;
                unsigned S2 = Zp & wA2;
                unsigned S1 = (Zp & wA1) | (~Zp & ~wB0);
                if (ck == 0 && g == 0) S2 &= ~1u;
                int c = Cin + sofar + __popc(S2 & lemask);
                sofar += __popc(S2);
                z = Z >> 31;
                bool tum = (S2 >> lane) & 1u;
                if (ck == 0 && g == 0 && lane == 0) {
                    ax += x0[b * 3 + 0]; ay += x0[b * 3 + 1]; az += x0[b * 3 + 2];
                } else if (!tum) {
                    float spd = ((S1 >> lane) & 1u) ? 5e-3f : 1e-3f;
                    int idx = c - 1;
                    idx = idx < 0 ? 0 : (idx > NTUM ? NTUM : idx);
                    ax += spd * s_e0s[idx * 3 + 0];
                    ay += spd * s_e0s[idx * 3 + 1];
                    az += spd * s_e0s[idx * 3 + 2];
                }
            }
#pragma unroll
            for (int o = 16; o; o >>= 1) {
                ax += __shfl_xor_sync(0xffffffffu, ax, o);
                ay += __shfl_xor_sync(0xffffffffu, ay, o);
                az += __shfl_xor_sync(0xffffffffu, az, o);
            }
            if (lane == 0) {   // offset of this chunk within the warp's range
                s_coffx[ck] = rx; s_coffy[ck] = ry; s_coffz[ck] = rz;
            }
            rx += ax; ry += ay; rz += az;
        }
        if (lane == 0) {
            s_wtot[w][0] = rx; s_wtot[w][1] = ry; s_wtot[w][2] = rz;
        }
    }
    __syncthreads();

    // ---------------- scan B: warp bases (double accumulation) ------------
    if (tid == 0) {
        double bx = 0.0, by = 0.0, bz = 0.0;
#pragma unroll
        for (int j = 0; j < NWW; ++j) {
            s_wbase[j][0] = (float)bx;
            s_wbase[j][1] = (float)by;
            s_wbase[j][2] = (float)bz;
            bx += (double)s_wtot[j][0];
            by += (double)s_wtot[j][1];
            bz += (double)s_wtot[j][2];
        }
    }
    __syncthreads();

    // ---------------- phase 5: recompute, scan, write ---------------------
    if (w < NWW) {
        float bx = s_wbase[w][0], by = s_wbase[w][1], bz = s_wbase[w][2];
        for (int ck = cs; ck < ce; ++ck) {
            unsigned e = s_entry[ck];
            unsigned z = e & 1u;
            int Cin = (int)(e >> 1);
            int sofar = 0;
            float cx = bx + s_coffx[ck];
            float cy = by + s_coffy[ck];
            float cz = bz + s_coffz[ck];
            int base = b * NSTEPS + ck * CS;
#pragma unroll
            for (int g = 0; g < NGRP; ++g) {
                const unsigned* p = &s_ball[(ck * NGRP + g) * 3];
                unsigned wA1 = p[0], wA2 = p[1], wB0 = p[2];
                unsigned Z = affineZ(wA1, wA2, wB0, z);
                unsigned Zp = (Z << 1) | z;
                unsigned S2 = Zp & wA2;
                unsigned S1 = (Zp & wA1) | (~Zp & ~wB0);
                if (ck == 0 && g == 0) S2 &= ~1u;
                int c = Cin + sofar + __popc(S2 & lemask);
                sofar += __popc(S2);
                z = Z >> 31;
                float vx, vy, vz;
                bool tum = (S2 >> lane) & 1u;
                if (ck == 0 && g == 0 && lane == 0) {
                    vx = x0[b * 3 + 0]; vy = x0[b * 3 + 1]; vz = x0[b * 3 + 2];
                } else if (tum) {
                    vx = vy = vz = 0.f;
                } else {
                    float spd = ((S1 >> lane) & 1u) ? 5e-3f : 1e-3f;
                    int idx = c - 1;
                    idx = idx < 0 ? 0 : (idx > NTUM ? NTUM : idx);
                    vx = spd * s_e0s[idx * 3 + 0];
                    vy = spd * s_e0s[idx * 3 + 1];
                    vz = spd * s_e0s[idx * 3 + 2];
                }
                // inclusive warp scan of float3
#pragma unroll
                for (int o = 1; o < 32; o <<= 1) {
                    float tx = __shfl_up_sync(0xffffffffu, vx, o);
                    float ty = __shfl_up_sync(0xffffffffu, vy, o);
                    float tz = __shfl_up_sync(0xffffffffu, vz, o);
                    if (lane >= o) { vx += tx; vy += ty; vz += tz; }
                }
                int t3 = (base + g * 32 + lane) * 3;
                out[t3 + 0] = cx + vx;
                out[t3 + 1] = cy + vy;
                out[t3 + 2] = cz + vz;
                cx += __shfl_sync(0xffffffffu, vx, 31);
                cy += __shfl_sync(0xffffffffu, vy, 31);
                cz += __shfl_sync(0xffffffffu, vz, 31);
            }
        }
    }
}

// ---------------- launch ----------------------------------------------------
extern "C" void kernel_launch(void* const* d_in, const int* in_sizes, int n_in,
                              void* d_out, int out_size) {
    const float* x0 = (const float*)d_in[0];
    const float* v0 = (const float*)d_in[1];
    const float* v1 = (const float*)d_in[2];
    const float* r0 = (const float*)d_in[3];
    const float* r1 = (const float*)d_in[4];
    const float* up = (const float*)d_in[5];
    const float* un = (const float*)d_in[6];
    float* X = (float*)d_out;

    k_fused<<<BATCH, THREADS>>>(x0, v0, v1, r0, r1, up, un, X);
}

// round 3
// speedup vs baseline: 2.9808x; 1.1788x over previous
#include <cuda_runtime.h>
#include <math.h>

#define BATCH   512
#define NSTEPS  20000
#define NTUM    64
#define NCHUNK  125      // chunks per batch
#define CS      160      // steps per chunk
#define NGRP    5        // 32-step groups per chunk
#define NWW     16       // worker warps per block
#define THREADS 544      // 16 worker warps + 1 frame warp

// ---------------- small vector helpers ----------------
struct F3 { float x, y, z; };
__device__ __forceinline__ F3 mk3(float x, float y, float z) { F3 r{x, y, z}; return r; }
__device__ __forceinline__ float dot3(F3 a, F3 b) { return a.x * b.x + a.y * b.y + a.z * b.z; }
__device__ __forceinline__ F3 cross3(F3 a, F3 b) {
    return mk3(a.y * b.z - a.z * b.y, a.z * b.x - a.x * b.z, a.x * b.y - a.y * b.x);
}
__device__ __forceinline__ F3 nrm3(F3 v) {
    float r = rsqrtf(v.x * v.x + v.y * v.y + v.z * v.z);
    return mk3(v.x * r, v.y * r, v.z * r);
}
__device__ __forceinline__ F3 ortho3(F3 v, F3 u) {
    float k = __fdividef(dot3(v, u), dot3(u, u));
    return mk3(v.x - k * u.x, v.y - k * u.y, v.z - k * u.z);
}
__device__ __forceinline__ F3 rodApply(F3 u, float c, float s, F3 v) {
    F3 cv = cross3(u, v);
    float d = dot3(u, v);
    float oc = 1.0f - c;
    return mk3(c * v.x + s * cv.x + oc * d * u.x,
               c * v.y + s * cv.y + oc * d * u.y,
               c * v.z + s * cv.z + oc * d * u.z);
}
__device__ __forceinline__ float cauchy_angle(float u, float sig) {
    float a = sig * tanf((float)M_PI * (u - 0.5f));   // mu = 0
    if (!isfinite(a)) a = 0.0f;
    return fmodf(a, (float)M_PI);
}

// ---------------- affine GF(2) prefix over 32 steps ----------------------
__device__ __forceinline__ unsigned affineZ(unsigned wA1, unsigned wA2,
                                            unsigned wB0, unsigned zin) {
    unsigned a = ~(wA1 | wA2);
    unsigned P = a ^ wB0;
    unsigned Q = wB0;
#pragma unroll
    for (int k = 1; k < 32; k <<= 1) {
        Q = Q ^ (P & (Q << k));
        P = P & ((P << k) | ((1u << k) - 1u));
    }
    return Q ^ (zin ? P : 0u);
}

__device__ __forceinline__ int clipIdx(int c) {
    int idx = c - 1;
    return idx < 0 ? 0 : (idx > NTUM ? NTUM : idx);
}

// ============================================================================
// Single fused kernel: one block per batch.
// ============================================================================
__global__ void __launch_bounds__(THREADS, 2)
k_fused(const float* __restrict__ x0, const float* __restrict__ v0,
        const float* __restrict__ v1, const float* __restrict__ r0,
        const float* __restrict__ r1, const float* __restrict__ up,
        const float* __restrict__ un, float* __restrict__ out) {
    __shared__ unsigned s_ball[NCHUNK * NGRP * 3];
    __shared__ unsigned s_cinfo[NCHUNK];     // exA|exB<<2|cntA<<4|cntB<<16|zero<<28
    __shared__ unsigned s_gmask[NCHUNK];     // per-group fast bits
    __shared__ unsigned s_entry[NCHUNK];     // z | C<<1
    __shared__ float    s_coffx[NCHUNK], s_coffy[NCHUNK], s_coffz[NCHUNK];
    __shared__ float    s_wtot[NWW][3];
    __shared__ float    s_wbase[NWW][3];
    __shared__ float    s_e0s[(NTUM + 1) * 3];
    __shared__ float    s_cp[NTUM], s_sp[NTUM], s_cn[NTUM], s_sn[NTUM];

    const int b    = blockIdx.x;
    const int tid  = threadIdx.x;
    const int w    = tid >> 5;
    const int lane = tid & 31;

    const float R01 = 1e-3f, R10 = 1e-3f;
    const float TH  = (float)(1.0 - 1e-3);
    const unsigned lemask = 0xffffffffu >> (31 - lane);

    // chunk range for worker warp w: warps 0..12 -> 8 chunks, 13..15 -> 7
    int cs = 0, ce = 0;
    if (w < NWW) {
        cs = (w < 13) ? w * 8 : 104 + (w - 13) * 7;
        ce = cs + ((w < 13) ? 8 : 7);
    }

    // ---------------- phase 1: ballots + per-chunk info / frame chain -----
    if (w == NWW) {
        for (int i = lane; i < NTUM; i += 32) {
            float ap = cauchy_angle(up[b * NTUM + i], 0.1f);
            float an = cauchy_angle(un[b * NTUM + i], 0.5f);
            s_cp[i] = cosf(ap); s_sp[i] = sinf(ap);
            s_cn[i] = cosf(an); s_sn[i] = sinf(an);
        }
        __syncwarp();
        if (lane == 0) {
            F3 a = mk3(v0[b * 3 + 0], v0[b * 3 + 1], v0[b * 3 + 2]);
            F3 c = mk3(v1[b * 3 + 0], v1[b * 3 + 1], v1[b * 3 + 2]);
            F3 e0 = nrm3(a);
            F3 e1 = nrm3(ortho3(c, e0));
            F3 e2 = nrm3(cross3(e0, e1));
            s_e0s[0] = e0.x; s_e0s[1] = e0.y; s_e0s[2] = e0.z;
            // rotations preserve orthonormality; keep 2 renorms/iter for drift
            for (int i = 0; i < NTUM; ++i) {
                float cp = s_cp[i], sp = s_sp[i];
                F3 n0 = rodApply(e2, cp, sp, e0);
                F3 n1 = rodApply(e2, cp, sp, e1);
                float cn = s_cn[i], sn = s_sn[i];
                e0 = nrm3(rodApply(n1, cn, sn, n0));
                e1 = n1;
                e2 = nrm3(cross3(e0, e1));
                s_e0s[(i + 1) * 3 + 0] = e0.x;
                s_e0s[(i + 1) * 3 + 1] = e0.y;
                s_e0s[(i + 1) * 3 + 2] = e0.z;
            }
        }
    } else {
        for (int ck = cs; ck < ce; ++ck) {
            int base = b * NSTEPS + ck * CS;
            unsigned zA = 1u, zB = 0u;
            int cntA = 0, cntB = 0;
            unsigned lastTA = 0, lastTB = 0;
            unsigned chunkOr = 0, gmask = 0;
#pragma unroll
            for (int g = 0; g < NGRP; ++g) {
                float a0 = r0[base + g * 32 + lane];
                float a1 = r1[base + g * 32 + lane];
                unsigned wA1 = __ballot_sync(0xffffffffu, a0 < R01);
                unsigned wA2 = __ballot_sync(0xffffffffu, a0 > TH);
                unsigned wB0 = __ballot_sync(0xffffffffu, a1 < R10);
                unsigned orw = wA1 | wA2 | wB0;
                chunkOr |= orw;
                bool fast = (orw == 0u) && !(ck == 0 && g == 0);
                if (fast) {
                    gmask |= 1u << g;
                    lastTA = lastTB = 0;
                    continue;                 // z, cnt unchanged
                }
                if (lane < 3) {
                    unsigned val = (lane == 0) ? wA1 : (lane == 1 ? wA2 : wB0);
                    s_ball[(ck * NGRP + g) * 3 + lane] = val;
                }
                unsigned ZA = affineZ(wA1, wA2, wB0, zA);
                unsigned ZB = affineZ(wA1, wA2, wB0, zB);
                unsigned S2A = ((ZA << 1) | zA) & wA2;
                unsigned S2B = ((ZB << 1) | zB) & wA2;
                if (ck == 0 && g == 0) { S2A &= ~1u; S2B &= ~1u; }
                cntA += __popc(S2A);
                cntB += __popc(S2B);
                zA = ZA >> 31;
                zB = ZB >> 31;
                lastTA = S2A >> 31;
                lastTB = S2B >> 31;
            }
            unsigned exA = zA ? 0u : (lastTA ? 2u : 1u);
            unsigned exB = zB ? 0u : (lastTB ? 2u : 1u);
            unsigned zero = (chunkOr == 0u && ck != 0) ? (1u << 28) : 0u;
            if (lane == 0) {
                s_cinfo[ck] = exA | (exB << 2) |
                              ((unsigned)cntA << 4) | ((unsigned)cntB << 16) | zero;
                s_gmask[ck] = gmask;
            }
        }
    }
    __syncthreads();

    // ---------------- scan A: chunk entry state + tumble prefix -----------
    if (tid == 0) {
        int s = 0;
        unsigned C = 0;
        for (int j = 0; j < NCHUNK; ++j) {
            unsigned z = (s == 0) ? 1u : 0u;
            s_entry[j] = z | (C << 1);
            unsigned info = s_cinfo[j];
            C += z ? ((info >> 4) & 0xFFFu) : ((info >> 16) & 0xFFFu);
            s = (int)(z ? (info & 3u) : ((info >> 2) & 3u));
        }
    }
    __syncthreads();

    // ---------------- phase 3: per-chunk velocity sums --------------------
    if (w < NWW) {
        float rx = 0.f, ry = 0.f, rz = 0.f;
        for (int ck = cs; ck < ce; ++ck) {
            unsigned e = s_entry[ck];
            unsigned z = e & 1u;
            int Cin = (int)(e >> 1);
            unsigned info = s_cinfo[ck];
            if (lane == 0) { s_coffx[ck] = rx; s_coffy[ck] = ry; s_coffz[ck] = rz; }
            if ((info >> 28) & 1u) {           // whole-chunk fast
                float spd = z ? 1e-3f : 5e-3f;
                int idx = clipIdx(Cin);
                rx += CS * spd * s_e0s[idx * 3 + 0];
                ry += CS * spd * s_e0s[idx * 3 + 1];
                rz += CS * spd * s_e0s[idx * 3 + 2];
                continue;
            }
            unsigned gm = s_gmask[ck];
            int sofar = 0;
            float ax = 0.f, ay = 0.f, az = 0.f;   // per-lane
            float ux = 0.f, uy = 0.f, uz = 0.f;   // warp-uniform
#pragma unroll
            for (int g = 0; g < NGRP; ++g) {
                if ((gm >> g) & 1u) {             // fast group
                    float spd = z ? 1e-3f : 5e-3f;
                    int idx = clipIdx(Cin + sofar);
                    ux += 32.f * spd * s_e0s[idx * 3 + 0];
                    uy += 32.f * spd * s_e0s[idx * 3 + 1];
                    uz += 32.f * spd * s_e0s[idx * 3 + 2];
                    continue;
                }
                const unsigned* p = &s_ball[(ck * NGRP + g) * 3];
                unsigned wA1 = p[0], wA2 = p[1], wB0 = p[2];
                unsigned Z = affineZ(wA1, wA2, wB0, z);
                unsigned Zp = (Z << 1) | z;
                unsigned S2 = Zp & wA2;
                unsigned S1 = (Zp & wA1) | (~Zp & ~wB0);
                if (ck == 0 && g == 0) S2 &= ~1u;
                int c = Cin + sofar + __popc(S2 & lemask);
                sofar += __popc(S2);
                z = Z >> 31;
                bool tum = (S2 >> lane) & 1u;
                if (ck == 0 && g == 0 && lane == 0) {
                    ax += x0[b * 3 + 0]; ay += x0[b * 3 + 1]; az += x0[b * 3 + 2];
                } else if (!tum) {
                    float spd = ((S1 >> lane) & 1u) ? 5e-3f : 1e-3f;
                    int idx = clipIdx(c);
                    ax += spd * s_e0s[idx * 3 + 0];
                    ay += spd * s_e0s[idx * 3 + 1];
                    az += spd * s_e0s[idx * 3 + 2];
                }
            }
#pragma unroll
            for (int o = 16; o; o >>= 1) {
                ax += __shfl_xor_sync(0xffffffffu, ax, o);
                ay += __shfl_xor_sync(0xffffffffu, ay, o);
                az += __shfl_xor_sync(0xffffffffu, az, o);
            }
            rx += ux + ax; ry += uy + ay; rz += uz + az;
        }
        if (lane == 0) {
            s_wtot[w][0] = rx; s_wtot[w][1] = ry; s_wtot[w][2] = rz;
        }
    }
    __syncthreads();

    // ---------------- scan B: warp bases (double accumulation) ------------
    if (tid == 0) {
        double bx = 0.0, by = 0.0, bz = 0.0;
#pragma unroll
        for (int j = 0; j < NWW; ++j) {
            s_wbase[j][0] = (float)bx;
            s_wbase[j][1] = (float)by;
            s_wbase[j][2] = (float)bz;
            bx += (double)s_wtot[j][0];
            by += (double)s_wtot[j][1];
            bz += (double)s_wtot[j][2];
        }
    }
    __syncthreads();

    // ---------------- phase 5: recompute, scan, write ---------------------
    if (w < NWW) {
        const float bxw = s_wbase[w][0], byw = s_wbase[w][1], bzw = s_wbase[w][2];
        for (int ck = cs; ck < ce; ++ck) {
            unsigned e = s_entry[ck];
            unsigned z = e & 1u;
            int Cin = (int)(e >> 1);
            unsigned info = s_cinfo[ck];
            float cx = bxw + s_coffx[ck];
            float cy = byw + s_coffy[ck];
            float cz = bzw + s_coffz[ck];
            int base = b * NSTEPS + ck * CS;
            if ((info >> 28) & 1u) {           // whole-chunk fast: linear ramp
                float spd = z ? 1e-3f : 5e-3f;
                int idx = clipIdx(Cin);
                float vx = spd * s_e0s[idx * 3 + 0];
                float vy = spd * s_e0s[idx * 3 + 1];
                float vz = spd * s_e0s[idx * 3 + 2];
#pragma unroll
                for (int g = 0; g < NGRP; ++g) {
                    float t = (float)(g * 32 + lane + 1);
                    int t3 = (base + g * 32 + lane) * 3;
                    out[t3 + 0] = fmaf(t, vx, cx);
                    out[t3 + 1] = fmaf(t, vy, cy);
                    out[t3 + 2] = fmaf(t, vz, cz);
                }
                continue;
            }
            unsigned gm = s_gmask[ck];
            int sofar = 0;
#pragma unroll
            for (int g = 0; g < NGRP; ++g) {
                if ((gm >> g) & 1u) {          // fast group: ramp
                    float spd = z ? 1e-3f : 5e-3f;
                    int idx = clipIdx(Cin + sofar);
                    float vx = spd * s_e0s[idx * 3 + 0];
                    float vy = spd * s_e0s[idx * 3 + 1];
                    float vz = spd * s_e0s[idx * 3 + 2];
                    float t = (float)(lane + 1);
                    int t3 = (base + g * 32 + lane) * 3;
                    out[t3 + 0] = fmaf(t, vx, cx);
                    out[t3 + 1] = fmaf(t, vy, cy);
                    out[t3 + 2] = fmaf(t, vz, cz);
                    cx = fmaf(32.f, vx, cx);
                    cy = fmaf(32.f, vy, cy);
                    cz = fmaf(32.f, vz, cz);
                    continue;
                }
                const unsigned* p = &s_ball[(ck * NGRP + g) * 3];
                unsigned wA1 = p[0], wA2 = p[1], wB0 = p[2];
                unsigned Z = affineZ(wA1, wA2, wB0, z);
                unsigned Zp = (Z << 1) | z;
                unsigned S2 = Zp & wA2;
                unsigned S1 = (Zp & wA1) | (~Zp & ~wB0);
                if (ck == 0 && g == 0) S2 &= ~1u;
                int c = Cin + sofar + __popc(S2 & lemask);
                sofar += __popc(S2);
                z = Z >> 31;
                float vx, vy, vz;
                bool tum = (S2 >> lane) & 1u;
                if (ck == 0 && g == 0 && lane == 0) {
                    vx = x0[b * 3 + 0]; vy = x0[b * 3 + 1]; vz = x0[b * 3 + 2];
                } else if (tum) {
                    vx = vy = vz = 0.f;
                } else {
                    float spd = ((S1 >> lane) & 1u) ? 5e-3f : 1e-3f;
                    int idx = clipIdx(c);
                    vx = spd * s_e0s[idx * 3 + 0];
                    vy = spd * s_e0s[idx * 3 + 1];
                    vz = spd * s_e0s[idx * 3 + 2];
                }
#pragma unroll
                for (int o = 1; o < 32; o <<= 1) {
                    float tx = __shfl_up_sync(0xffffffffu, vx, o);
                    float ty = __shfl_up_sync(0xffffffffu, vy, o);
                    float tz = __shfl_up_sync(0xffffffffu, vz, o);
                    if (lane >= o) { vx += tx; vy += ty; vz += tz; }
                }
                int t3 = (base + g * 32 + lane) * 3;
                out[t3 + 0] = cx + vx;
                out[t3 + 1] = cy + vy;
                out[t3 + 2] = cz + vz;
                cx += __shfl_sync(0xffffffffu, vx, 31);
                cy += __shfl_sync(0xffffffffu, vy, 31);
                cz += __shfl_sync(0xffffffffu, vz, 31);
            }
        }
    }
}

// ---------------- launch ----------------------------------------------------
extern "C" void kernel_launch(void* const* d_in, const int* in_sizes, int n_in,
                              void* d_out, int out_size) {
    const float* x0 = (const float*)d_in[0];
    const float* v0 = (const float*)d_in[1];
    const float* v1 = (const float*)d_in[2];
    const float* r0 = (const float*)d_in[3];
    const float* r1 = (const float*)d_in[4];
    const float* up = (const float*)d_in[5];
    const float* un = (const float*)d_in[6];
    float* X = (float*)d_out;

    k_fused<<<BATCH, THREADS>>>(x0, v0, v1, r0, r1, up, un, X);
}

// round 4
// speedup vs baseline: 3.9530x; 1.3262x over previous
#include <cuda_runtime.h>
#include <math.h>

#define BATCH   512
#define NSTEPS  20000
#define NTUM    64
#define NCHUNK  125      // chunks per batch
#define CS      160      // steps per chunk
#define NGRP    5        // 32-step groups per chunk
#define NWW     16       // worker warps per block
#define THREADS 544      // 16 worker warps + 1 frame warp

// ---------------- small vector helpers ----------------
struct F3 { float x, y, z; };
__device__ __forceinline__ F3 mk3(float x, float y, float z) { F3 r{x, y, z}; return r; }
__device__ __forceinline__ float dot3(F3 a, F3 b) { return a.x * b.x + a.y * b.y + a.z * b.z; }
__device__ __forceinline__ F3 cross3(F3 a, F3 b) {
    return mk3(a.y * b.z - a.z * b.y, a.z * b.x - a.x * b.z, a.x * b.y - a.y * b.x);
}
__device__ __forceinline__ F3 nrm3(F3 v) {
    float r = rsqrtf(v.x * v.x + v.y * v.y + v.z * v.z);
    return mk3(v.x * r, v.y * r, v.z * r);
}
__device__ __forceinline__ F3 ortho3(F3 v, F3 u) {
    float k = __fdividef(dot3(v, u), dot3(u, u));
    return mk3(v.x - k * u.x, v.y - k * u.y, v.z - k * u.z);
}
__device__ __forceinline__ float cauchy_angle(float u, float sig) {
    float a = sig * tanf((float)M_PI * (u - 0.5f));   // mu = 0
    if (!isfinite(a)) a = 0.0f;
    return fmodf(a, (float)M_PI);
}
// 3x3 row-major multiply: C = A * B
__device__ __forceinline__ void mm3(float* C, const float* A, const float* B) {
#pragma unroll
    for (int i = 0; i < 3; ++i)
#pragma unroll
        for (int j = 0; j < 3; ++j)
            C[3 * i + j] = A[3 * i + 0] * B[j] + A[3 * i + 1] * B[3 + j] +
                           A[3 * i + 2] * B[6 + j];
}

// ---------------- affine GF(2) prefix over 32 steps ----------------------
__device__ __forceinline__ unsigned affineZ(unsigned wA1, unsigned wA2,
                                            unsigned wB0, unsigned zin) {
    unsigned a = ~(wA1 | wA2);
    unsigned P = a ^ wB0;
    unsigned Q = wB0;
#pragma unroll
    for (int k = 1; k < 32; k <<= 1) {
        Q = Q ^ (P & (Q << k));
        P = P & ((P << k) | ((1u << k) - 1u));
    }
    return Q ^ (zin ? P : 0u);
}

__device__ __forceinline__ int clipIdx(int c) {
    int idx = c - 1;
    return idx < 0 ? 0 : (idx > NTUM ? NTUM : idx);
}

// chunk map word: bit0 = z_out(entry z=1), bit1 = z_out(entry z=0),
// bits[2,17) = cnt(entry=1), bits[17,32) = cnt(entry=0). Identity = 1.
__device__ __forceinline__ unsigned composeMap(unsigned m1, unsigned m2) {
    unsigned z1 = m1 & 1u;
    unsigned z0 = (m1 >> 1) & 1u;
    unsigned c2a = (m2 >> 2) & 0x7FFFu;
    unsigned c2b = (m2 >> 17) & 0x7FFFu;
    unsigned o1 = z1 ? (m2 & 1u) : ((m2 >> 1) & 1u);
    unsigned o0 = z0 ? (m2 & 1u) : ((m2 >> 1) & 1u);
    unsigned d1 = ((m1 >> 2) & 0x7FFFu) + (z1 ? c2a : c2b);
    unsigned d0 = ((m1 >> 17) & 0x7FFFu) + (z0 ? c2a : c2b);
    return o1 | (o0 << 1) | (d1 << 2) | (d0 << 17);
}

// ============================================================================
// Single fused kernel: one block per batch.
// ============================================================================
__global__ void __launch_bounds__(THREADS, 2)
k_fused(const float* __restrict__ x0, const float* __restrict__ v0,
        const float* __restrict__ v1, const float* __restrict__ r0,
        const float* __restrict__ r1, const float* __restrict__ up,
        const float* __restrict__ un, float* __restrict__ out) {
    __shared__ unsigned s_ball[NCHUNK * NGRP * 3];
    __shared__ unsigned s_cinfo[NCHUNK];     // packed chunk map
    __shared__ unsigned s_gmask[NCHUNK];     // per-group fast bits (0x1F = all fast)
    __shared__ unsigned s_entry[NCHUNK];     // z | C<<1
    __shared__ float    s_coffx[NCHUNK], s_coffy[NCHUNK], s_coffz[NCHUNK];
    __shared__ float    s_wtot[NWW][3];
    __shared__ float    s_wbase[NWW][3];
    __shared__ float    s_e0s[(NTUM + 1) * 3];
    __shared__ __align__(16) float s_stage[NWW][CS * 3];   // 30 KB staging

    const int b    = blockIdx.x;
    const int tid  = threadIdx.x;
    const int w    = tid >> 5;
    const int lane = tid & 31;

    const float R01 = 1e-3f, R10 = 1e-3f;
    const float TH  = (float)(1.0 - 1e-3);
    const unsigned FULL = 0xffffffffu;
    const unsigned lemask = FULL >> (31 - lane);

    // chunk range for worker warp w: warps 0..12 -> 8 chunks, 13..15 -> 7
    int cs = 0, ce = 0;
    if (w < NWW) {
        cs = (w < 13) ? w * 8 : 104 + (w - 13) * 7;
        ce = cs + ((w < 13) ? 8 : 7);
    }

    // ---------------- phase 1: ballots + chunk maps / frame matrix scan ---
    if (w == NWW) {
        // lane handles tumbles 2*lane, 2*lane+1
        int i0 = 2 * lane, i1 = 2 * lane + 1;
        float ap0 = cauchy_angle(up[b * NTUM + i0], 0.1f);
        float an0 = cauchy_angle(un[b * NTUM + i0], 0.5f);
        float ap1 = cauchy_angle(up[b * NTUM + i1], 0.1f);
        float an1 = cauchy_angle(un[b * NTUM + i1], 0.5f);
        float cp0 = cosf(ap0), sp0 = sinf(ap0), cb0 = cosf(an0), sb0 = sinf(an0);
        float cp1 = cosf(ap1), sp1 = sinf(ap1), cb1 = cosf(an1), sb1 = sinf(an1);
        // L = Rz(ap) * Ry(an), row-major
        float A[9] = { cp0 * cb0, -sp0, cp0 * sb0,
                       sp0 * cb0,  cp0, sp0 * sb0,
                       -sb0,       0.f, cb0 };
        float L1m[9] = { cp1 * cb1, -sp1, cp1 * sb1,
                         sp1 * cb1,  cp1, sp1 * sb1,
                         -sb1,       0.f, cb1 };
        float P[9];
        mm3(P, A, L1m);                       // pair product L_{2l} * L_{2l+1}
        // inclusive left-to-right warp scan of matrix products
#pragma unroll
        for (int k = 1; k < 32; k <<= 1) {
            float U[9];
#pragma unroll
            for (int q = 0; q < 9; ++q) U[q] = __shfl_up_sync(FULL, P[q], k);
            float T[9];
            mm3(T, U, P);
            if (lane >= k) {
#pragma unroll
                for (int q = 0; q < 9; ++q) P[q] = T[q];
            }
        }
        float E[9];
#pragma unroll
        for (int q = 0; q < 9; ++q) E[q] = __shfl_up_sync(FULL, P[q], 1);
        if (lane == 0) {
            E[0] = 1.f; E[1] = 0.f; E[2] = 0.f;
            E[3] = 0.f; E[4] = 1.f; E[5] = 0.f;
            E[6] = 0.f; E[7] = 0.f; E[8] = 1.f;
        }
        // initial frame (redundant per-lane; broadcast loads)
        F3 a = mk3(v0[b * 3 + 0], v0[b * 3 + 1], v0[b * 3 + 2]);
        F3 c = mk3(v1[b * 3 + 0], v1[b * 3 + 1], v1[b * 3 + 2]);
        F3 e0 = nrm3(a);
        F3 e1 = nrm3(ortho3(c, e0));
        F3 e2 = nrm3(cross3(e0, e1));
        if (lane == 0) { s_e0s[0] = e0.x; s_e0s[1] = e0.y; s_e0s[2] = e0.z; }
        // e0s[2l+1] = F0 * (E * col0(A))
        float a0x = A[0], a0y = A[3], a0z = A[6];
        float q1x = E[0] * a0x + E[1] * a0y + E[2] * a0z;
        float q1y = E[3] * a0x + E[4] * a0y + E[5] * a0z;
        float q1z = E[6] * a0x + E[7] * a0y + E[8] * a0z;
        int o1 = (2 * lane + 1) * 3;
        s_e0s[o1 + 0] = q1x * e0.x + q1y * e1.x + q1z * e2.x;
        s_e0s[o1 + 1] = q1x * e0.y + q1y * e1.y + q1z * e2.y;
        s_e0s[o1 + 2] = q1x * e0.z + q1y * e1.z + q1z * e2.z;
        // e0s[2l+2] = F0 * col0(P)
        float q2x = P[0], q2y = P[3], q2z = P[6];
        int o2 = (2 * lane + 2) * 3;
        s_e0s[o2 + 0] = q2x * e0.x + q2y * e1.x + q2z * e2.x;
        s_e0s[o2 + 1] = q2x * e0.y + q2y * e1.y + q2z * e2.y;
        s_e0s[o2 + 2] = q2x * e0.z + q2y * e1.z + q2z * e2.z;
    } else {
        for (int ck = cs; ck < ce; ++ck) {
            int base = b * NSTEPS + ck * CS;
            unsigned zA = 1u, zB = 0u;
            unsigned cntA = 0, cntB = 0, gmask = 0;
#pragma unroll
            for (int g = 0; g < NGRP; ++g) {
                float a0 = r0[base + g * 32 + lane];
                float a1 = r1[base + g * 32 + lane];
                unsigned wA1 = __ballot_sync(FULL, a0 < R01);
                unsigned wA2 = __ballot_sync(FULL, a0 > TH);
                unsigned wB0 = __ballot_sync(FULL, a1 < R10);
                bool fast = ((wA1 | wA2 | wB0) == 0u) && !(ck == 0 && g == 0);
                if (fast) { gmask |= 1u << g; continue; }
                if (lane < 3) {
                    unsigned val = (lane == 0) ? wA1 : (lane == 1 ? wA2 : wB0);
                    s_ball[(ck * NGRP + g) * 3 + lane] = val;
                }
                unsigned ZA = affineZ(wA1, wA2, wB0, zA);
                unsigned ZB = affineZ(wA1, wA2, wB0, zB);
                unsigned S2A = ((ZA << 1) | zA) & wA2;
                unsigned S2B = ((ZB << 1) | zB) & wA2;
                if (ck == 0 && g == 0) { S2A &= ~1u; S2B &= ~1u; }
                cntA += __popc(S2A);
                cntB += __popc(S2B);
                zA = ZA >> 31;
                zB = ZB >> 31;
            }
            if (lane == 0) {
                s_cinfo[ck] = zA | (zB << 1) | (cntA << 2) | (cntB << 17);
                s_gmask[ck] = gmask;
            }
        }
    }
    __syncthreads();

    // ---------------- scan A: warp-parallel chunk map scan (warp 0) -------
    if (w == 0) {
        unsigned m = 1u;                       // identity
        int ck0 = lane * 4;
#pragma unroll
        for (int j = 0; j < 4; ++j) {
            int ck = ck0 + j;
            if (ck < NCHUNK) m = composeMap(m, s_cinfo[ck]);
        }
#pragma unroll
        for (int k = 1; k < 32; k <<= 1) {
            unsigned mu = __shfl_up_sync(FULL, m, k);
            unsigned mc = composeMap(mu, m);
            if (lane >= k) m = mc;
        }
        unsigned ex = __shfl_up_sync(FULL, m, 1);
        if (lane == 0) ex = 1u;
        unsigned z = ex & 1u;                  // apply prefix to init (z=1, C=0)
        unsigned C = (ex >> 2) & 0x7FFFu;
#pragma unroll
        for (int j = 0; j < 4; ++j) {
            int ck = ck0 + j;
            if (ck < NCHUNK) {
                s_entry[ck] = z | (C << 1);
                unsigned mm = s_cinfo[ck];
                C += z ? ((mm >> 2) & 0x7FFFu) : ((mm >> 17) & 0x7FFFu);
                z = z ? (mm & 1u) : ((mm >> 1) & 1u);
            }
        }
    }
    __syncthreads();

    // ---------------- phase 3: per-chunk velocity sums --------------------
    if (w < NWW) {
        float rx = 0.f, ry = 0.f, rz = 0.f;
        for (int ck = cs; ck < ce; ++ck) {
            unsigned e = s_entry[ck];
            unsigned z = e & 1u;
            int Cin = (int)(e >> 1);
            if (lane == 0) { s_coffx[ck] = rx; s_coffy[ck] = ry; s_coffz[ck] = rz; }
            unsigned gm = s_gmask[ck];
            if (gm == 0x1Fu) {                 // whole-chunk fast
                float spd = z ? 1e-3f : 5e-3f;
                int idx = clipIdx(Cin);
                rx += CS * spd * s_e0s[idx * 3 + 0];
                ry += CS * spd * s_e0s[idx * 3 + 1];
                rz += CS * spd * s_e0s[idx * 3 + 2];
                continue;
            }
            int sofar = 0;
            float ax = 0.f, ay = 0.f, az = 0.f;   // per-lane
            float ux = 0.f, uy = 0.f, uz = 0.f;   // warp-uniform
#pragma unroll
            for (int g = 0; g < NGRP; ++g) {
                if ((gm >> g) & 1u) {             // fast group
                    float spd = z ? 1e-3f : 5e-3f;
                    int idx = clipIdx(Cin + sofar);
                    ux += 32.f * spd * s_e0s[idx * 3 + 0];
                    uy += 32.f * spd * s_e0s[idx * 3 + 1];
                    uz += 32.f * spd * s_e0s[idx * 3 + 2];
                    continue;
                }
                const unsigned* p = &s_ball[(ck * NGRP + g) * 3];
                unsigned wA1 = p[0], wA2 = p[1], wB0 = p[2];
                unsigned Z = affineZ(wA1, wA2, wB0, z);
                unsigned Zp = (Z << 1) | z;
                unsigned S2 = Zp & wA2;
                unsigned S1 = (Zp & wA1) | (~Zp & ~wB0);
                if (ck == 0 && g == 0) S2 &= ~1u;
                int c = Cin + sofar + __popc(S2 & lemask);
                sofar += __popc(S2);
                z = Z >> 31;
                bool tum = (S2 >> lane) & 1u;
                if (ck == 0 && g == 0 && lane == 0) {
                    ax += x0[b * 3 + 0]; ay += x0[b * 3 + 1]; az += x0[b * 3 + 2];
                } else if (!tum) {
                    float spd = ((S1 >> lane) & 1u) ? 5e-3f : 1e-3f;
                    int idx = clipIdx(c);
                    ax += spd * s_e0s[idx * 3 + 0];
                    ay += spd * s_e0s[idx * 3 + 1];
                    az += spd * s_e0s[idx * 3 + 2];
                }
            }
#pragma unroll
            for (int o = 16; o; o >>= 1) {
                ax += __shfl_xor_sync(FULL, ax, o);
                ay += __shfl_xor_sync(FULL, ay, o);
                az += __shfl_xor_sync(FULL, az, o);
            }
            rx += ux + ax; ry += uy + ay; rz += uz + az;
        }
        if (lane == 0) {
            s_wtot[w][0] = rx; s_wtot[w][1] = ry; s_wtot[w][2] = rz;
        }
    }
    __syncthreads();

    // ---------------- scan B: warp bases (16-lane shuffle scan, warp 0) ---
    if (w == 0) {
        float tx = 0.f, ty = 0.f, tz = 0.f;
        if (lane < NWW) { tx = s_wtot[lane][0]; ty = s_wtot[lane][1]; tz = s_wtot[lane][2]; }
#pragma unroll
        for (int k = 1; k < 16; k <<= 1) {
            float sx = __shfl_up_sync(FULL, tx, k);
            float sy = __shfl_up_sync(FULL, ty, k);
            float sz = __shfl_up_sync(FULL, tz, k);
            if (lane >= k) { tx += sx; ty += sy; tz += sz; }
        }
        float bx = __shfl_up_sync(FULL, tx, 1);
        float by = __shfl_up_sync(FULL, ty, 1);
        float bz = __shfl_up_sync(FULL, tz, 1);
        if (lane == 0) { bx = by = bz = 0.f; }
        if (lane < NWW) { s_wbase[lane][0] = bx; s_wbase[lane][1] = by; s_wbase[lane][2] = bz; }
    }
    __syncthreads();

    // ---------------- phase 5: recompute, scan, stage, coalesced write ----
    if (w < NWW) {
        const float bxw = s_wbase[w][0], byw = s_wbase[w][1], bzw = s_wbase[w][2];
        float* st = &s_stage[w][0];
        for (int ck = cs; ck < ce; ++ck) {
            unsigned e = s_entry[ck];
            unsigned z = e & 1u;
            int Cin = (int)(e >> 1);
            float cx = bxw + s_coffx[ck];
            float cy = byw + s_coffy[ck];
            float cz = bzw + s_coffz[ck];
            unsigned gm = s_gmask[ck];
            if (gm == 0x1Fu) {                 // whole-chunk fast: linear ramp
                float spd = z ? 1e-3f : 5e-3f;
                int idx = clipIdx(Cin);
                float vx = spd * s_e0s[idx * 3 + 0];
                float vy = spd * s_e0s[idx * 3 + 1];
                float vz = spd * s_e0s[idx * 3 + 2];
#pragma unroll
                for (int g = 0; g < NGRP; ++g) {
                    float t = (float)(g * 32 + lane + 1);
                    int o = (g * 32 + lane) * 3;
                    st[o + 0] = fmaf(t, vx, cx);
                    st[o + 1] = fmaf(t, vy, cy);
                    st[o + 2] = fmaf(t, vz, cz);
                }
            } else {
                int sofar = 0;
#pragma unroll
                for (int g = 0; g < NGRP; ++g) {
                    int o = (g * 32 + lane) * 3;
                    if ((gm >> g) & 1u) {      // fast group: ramp
                        float spd = z ? 1e-3f : 5e-3f;
                        int idx = clipIdx(Cin + sofar);
                        float vx = spd * s_e0s[idx * 3 + 0];
                        float vy = spd * s_e0s[idx * 3 + 1];
                        float vz = spd * s_e0s[idx * 3 + 2];
                        float t = (float)(lane + 1);
                        st[o + 0] = fmaf(t, vx, cx);
                        st[o + 1] = fmaf(t, vy, cy);
                        st[o + 2] = fmaf(t, vz, cz);
                        cx = fmaf(32.f, vx, cx);
                        cy = fmaf(32.f, vy, cy);
                        cz = fmaf(32.f, vz, cz);
                        continue;
                    }
                    const unsigned* p = &s_ball[(ck * NGRP + g) * 3];
                    unsigned wA1 = p[0], wA2 = p[1], wB0 = p[2];
                    unsigned Z = affineZ(wA1, wA2, wB0, z);
                    unsigned Zp = (Z << 1) | z;
                    unsigned S2 = Zp & wA2;
                    unsigned S1 = (Zp & wA1) | (~Zp & ~wB0);
                    if (ck == 0 && g == 0) S2 &= ~1u;
                    int c = Cin + sofar + __popc(S2 & lemask);
                    sofar += __popc(S2);
                    z = Z >> 31;
                    float vx, vy, vz;
                    bool tum = (S2 >> lane) & 1u;
                    if (ck == 0 && g == 0 && lane == 0) {
                        vx = x0[b * 3 + 0]; vy = x0[b * 3 + 1]; vz = x0[b * 3 + 2];
                    } else if (tum) {
                        vx = vy = vz = 0.f;
                    } else {
                        float spd = ((S1 >> lane) & 1u) ? 5e-3f : 1e-3f;
                        int idx = clipIdx(c);
                        vx = spd * s_e0s[idx * 3 + 0];
                        vy = spd * s_e0s[idx * 3 + 1];
                        vz = spd * s_e0s[idx * 3 + 2];
                    }
#pragma unroll
                    for (int oo = 1; oo < 32; oo <<= 1) {
                        float txu = __shfl_up_sync(FULL, vx, oo);
                        float tyu = __shfl_up_sync(FULL, vy, oo);
                        float tzu = __shfl_up_sync(FULL, vz, oo);
                        if (lane >= oo) { vx += txu; vy += tyu; vz += tzu; }
                    }
                    st[o + 0] = cx + vx;
                    st[o + 1] = cy + vy;
                    st[o + 2] = cz + vz;
                    cx += __shfl_sync(FULL, vx, 31);
                    cy += __shfl_sync(FULL, vy, 31);
                    cz += __shfl_sync(FULL, vz, 31);
                }
            }
            __syncwarp();
            // coalesced copy: 480 floats = 120 float4
            float4* o4 = reinterpret_cast<float4*>(out + (size_t)(b * NSTEPS + ck * CS) * 3);
            const float4* s4 = reinterpret_cast<const float4*>(st);
#pragma unroll
            for (int i = 0; i < 4; ++i) {
                int idx4 = i * 32 + lane;
                if (idx4 < 120) o4[idx4] = s4[idx4];
            }
            __syncwarp();
        }
    }
}

// ---------------- launch ----------------------------------------------------
extern "C" void kernel_launch(void* const* d_in, const int* in_sizes, int n_in,
                              void* d_out, int out_size) {
    const float* x0 = (const float*)d_in[0];
    const float* v0 = (const float*)d_in[1];
    const float* v1 = (const float*)d_in[2];
    const float* r0 = (const float*)d_in[3];
    const float* r1 = (const float*)d_in[4];
    const float* up = (const float*)d_in[5];
    const float* un = (const float*)d_in[6];
    float* X = (float*)d_out;

    k_fused<<<BATCH, THREADS>>>(x0, v0, v1, r0, r1, up, un, X);
}

// round 5
// speedup vs baseline: 4.2569x; 1.0769x over previous
#include <cuda_runtime.h>
#include <math.h>

#define BATCH   512
#define NSTEPS  20000
#define NTUM    64
#define NCHUNK  125                 // chunks per batch
#define CS      160                 // steps per chunk
#define NGRP    5                   // 32-step groups per chunk
#define NCTOT   (BATCH * NCHUNK)    // 64000 chunks total

#define K1_WORK_BLOCKS  2000        // 8 warps * 4 chunks = 32 chunks/block
#define K1_FRAME_BLOCKS 64          // 8 warps/block * 64 = 512 frame warps
#define K3_BLOCKS       2048        // 4 segs per batch

// ---------------- global scratch (L2 resident, ~5.5 MB) ----------------
__device__ unsigned g_ball [NCTOT * NGRP * 3];   // 3.84 MB ballots
__device__ unsigned g_cinfo[NCTOT];              // packed chunk maps
__device__ unsigned g_gmask[NCTOT];              // per-group fast bits
__device__ unsigned g_entry[NCTOT];              // z | C<<1
__device__ float    g_off  [NCTOT * 3];          // chunk base positions
__device__ float    g_e0s  [BATCH * (NTUM + 1) * 3];

// ---------------- small vector helpers ----------------
struct F3 { float x, y, z; };
__device__ __forceinline__ F3 mk3(float x, float y, float z) { F3 r{x, y, z}; return r; }
__device__ __forceinline__ float dot3(F3 a, F3 b) { return a.x * b.x + a.y * b.y + a.z * b.z; }
__device__ __forceinline__ F3 cross3(F3 a, F3 b) {
    return mk3(a.y * b.z - a.z * b.y, a.z * b.x - a.x * b.z, a.x * b.y - a.y * b.x);
}
__device__ __forceinline__ F3 nrm3(F3 v) {
    float r = rsqrtf(v.x * v.x + v.y * v.y + v.z * v.z);
    return mk3(v.x * r, v.y * r, v.z * r);
}
__device__ __forceinline__ F3 ortho3(F3 v, F3 u) {
    float k = __fdividef(dot3(v, u), dot3(u, u));
    return mk3(v.x - k * u.x, v.y - k * u.y, v.z - k * u.z);
}
__device__ __forceinline__ float cauchy_angle(float u, float sig) {
    float a = sig * tanf((float)M_PI * (u - 0.5f));   // mu = 0
    if (!isfinite(a)) a = 0.0f;
    return fmodf(a, (float)M_PI);
}
__device__ __forceinline__ void mm3(float* C, const float* A, const float* B) {
#pragma unroll
    for (int i = 0; i < 3; ++i)
#pragma unroll
        for (int j = 0; j < 3; ++j)
            C[3 * i + j] = A[3 * i + 0] * B[j] + A[3 * i + 1] * B[3 + j] +
                           A[3 * i + 2] * B[6 + j];
}

// ---------------- affine GF(2) prefix over 32 steps ----------------------
__device__ __forceinline__ unsigned affineZ(unsigned wA1, unsigned wA2,
                                            unsigned wB0, unsigned zin) {
    unsigned a = ~(wA1 | wA2);
    unsigned P = a ^ wB0;
    unsigned Q = wB0;
#pragma unroll
    for (int k = 1; k < 32; k <<= 1) {
        Q = Q ^ (P & (Q << k));
        P = P & ((P << k) | ((1u << k) - 1u));
    }
    return Q ^ (zin ? P : 0u);
}

__device__ __forceinline__ int clipIdx(int c) {
    int idx = c - 1;
    return idx < 0 ? 0 : (idx > NTUM ? NTUM : idx);
}

// chunk map: bit0=z_out(entry z=1), bit1=z_out(entry z=0),
// [2,17)=cnt(entry=1), [17,32)=cnt(entry=0). Identity = 1.
__device__ __forceinline__ unsigned composeMap(unsigned m1, unsigned m2) {
    unsigned z1 = m1 & 1u;
    unsigned z0 = (m1 >> 1) & 1u;
    unsigned c2a = (m2 >> 2) & 0x7FFFu;
    unsigned c2b = (m2 >> 17) & 0x7FFFu;
    unsigned o1 = z1 ? (m2 & 1u) : ((m2 >> 1) & 1u);
    unsigned o0 = z0 ? (m2 & 1u) : ((m2 >> 1) & 1u);
    unsigned d1 = ((m1 >> 2) & 0x7FFFu) + (z1 ? c2a : c2b);
    unsigned d0 = ((m1 >> 17) & 0x7FFFu) + (z0 ? c2a : c2b);
    return o1 | (o0 << 1) | (d1 << 2) | (d0 << 17);
}

// ============================================================================
// K1: ballots + chunk maps (full-chip parallel) + frame matrix scan
// ============================================================================
__global__ void __launch_bounds__(256)
k1_ballots(const float* __restrict__ r0, const float* __restrict__ r1,
           const float* __restrict__ v0, const float* __restrict__ v1,
           const float* __restrict__ up, const float* __restrict__ un) {
    const int wid  = threadIdx.x >> 5;
    const int lane = threadIdx.x & 31;
    const unsigned FULL = 0xffffffffu;
    const float R01 = 1e-3f, R10 = 1e-3f;
    const float TH  = (float)(1.0 - 1e-3);

    if (blockIdx.x >= K1_WORK_BLOCKS) {
        // -------- frame warps: one batch per warp, matrix prefix scan ------
        int b = (blockIdx.x - K1_WORK_BLOCKS) * 8 + wid;
        if (b >= BATCH) return;
        int i0 = 2 * lane, i1 = 2 * lane + 1;
        float ap0 = cauchy_angle(up[b * NTUM + i0], 0.1f);
        float an0 = cauchy_angle(un[b * NTUM + i0], 0.5f);
        float ap1 = cauchy_angle(up[b * NTUM + i1], 0.1f);
        float an1 = cauchy_angle(un[b * NTUM + i1], 0.5f);
        float cp0 = cosf(ap0), sp0 = sinf(ap0), cb0 = cosf(an0), sb0 = sinf(an0);
        float cp1 = cosf(ap1), sp1 = sinf(ap1), cb1 = cosf(an1), sb1 = sinf(an1);
        float A[9] = { cp0 * cb0, -sp0, cp0 * sb0,
                       sp0 * cb0,  cp0, sp0 * sb0,
                       -sb0,       0.f, cb0 };
        float L1m[9] = { cp1 * cb1, -sp1, cp1 * sb1,
                         sp1 * cb1,  cp1, sp1 * sb1,
                         -sb1,       0.f, cb1 };
        float P[9];
        mm3(P, A, L1m);
#pragma unroll
        for (int k = 1; k < 32; k <<= 1) {
            float U[9];
#pragma unroll
            for (int q = 0; q < 9; ++q) U[q] = __shfl_up_sync(FULL, P[q], k);
            float T[9];
            mm3(T, U, P);
            if (lane >= k) {
#pragma unroll
                for (int q = 0; q < 9; ++q) P[q] = T[q];
            }
        }
        float E[9];
#pragma unroll
        for (int q = 0; q < 9; ++q) E[q] = __shfl_up_sync(FULL, P[q], 1);
        if (lane == 0) {
            E[0] = 1.f; E[1] = 0.f; E[2] = 0.f;
            E[3] = 0.f; E[4] = 1.f; E[5] = 0.f;
            E[6] = 0.f; E[7] = 0.f; E[8] = 1.f;
        }
        F3 a = mk3(v0[b * 3 + 0], v0[b * 3 + 1], v0[b * 3 + 2]);
        F3 c = mk3(v1[b * 3 + 0], v1[b * 3 + 1], v1[b * 3 + 2]);
        F3 e0 = nrm3(a);
        F3 e1 = nrm3(ortho3(c, e0));
        F3 e2 = nrm3(cross3(e0, e1));
        float* eo = &g_e0s[b * (NTUM + 1) * 3];
        if (lane == 0) { eo[0] = e0.x; eo[1] = e0.y; eo[2] = e0.z; }
        float a0x = A[0], a0y = A[3], a0z = A[6];
        float q1x = E[0] * a0x + E[1] * a0y + E[2] * a0z;
        float q1y = E[3] * a0x + E[4] * a0y + E[5] * a0z;
        float q1z = E[6] * a0x + E[7] * a0y + E[8] * a0z;
        int o1 = (2 * lane + 1) * 3;
        eo[o1 + 0] = q1x * e0.x + q1y * e1.x + q1z * e2.x;
        eo[o1 + 1] = q1x * e0.y + q1y * e1.y + q1z * e2.y;
        eo[o1 + 2] = q1x * e0.z + q1y * e1.z + q1z * e2.z;
        float q2x = P[0], q2y = P[3], q2z = P[6];
        int o2 = (2 * lane + 2) * 3;
        eo[o2 + 0] = q2x * e0.x + q2y * e1.x + q2z * e2.x;
        eo[o2 + 1] = q2x * e0.y + q2y * e1.y + q2z * e2.y;
        eo[o2 + 2] = q2x * e0.z + q2y * e1.z + q2z * e2.z;
        return;
    }

    // -------- worker warps: 4 chunks each, batch-agnostic ------------------
    int wgid = blockIdx.x * 8 + wid;          // 0..15999
#pragma unroll
    for (int j = 0; j < 4; ++j) {
        int c = wgid * 4 + j;                 // 0..63999
        int b = c / NCHUNK;
        int ck = c - b * NCHUNK;
        int base = b * NSTEPS + ck * CS;
        unsigned zA = 1u, zB = 0u;
        unsigned cntA = 0, cntB = 0, gmask = 0;
#pragma unroll
        for (int g = 0; g < NGRP; ++g) {
            float a0 = r0[base + g * 32 + lane];
            float a1 = r1[base + g * 32 + lane];
            unsigned wA1 = __ballot_sync(FULL, a0 < R01);
            unsigned wA2 = __ballot_sync(FULL, a0 > TH);
            unsigned wB0 = __ballot_sync(FULL, a1 < R10);
            bool fast = ((wA1 | wA2 | wB0) == 0u) && !(ck == 0 && g == 0);
            if (fast) { gmask |= 1u << g; continue; }
            if (lane < 3) {
                unsigned val = (lane == 0) ? wA1 : (lane == 1 ? wA2 : wB0);
                g_ball[(c * NGRP + g) * 3 + lane] = val;
            }
            unsigned ZA = affineZ(wA1, wA2, wB0, zA);
            unsigned ZB = affineZ(wA1, wA2, wB0, zB);
            unsigned S2A = ((ZA << 1) | zA) & wA2;
            unsigned S2B = ((ZB << 1) | zB) & wA2;
            if (ck == 0 && g == 0) { S2A &= ~1u; S2B &= ~1u; }
            cntA += __popc(S2A);
            cntB += __popc(S2B);
            zA = ZA >> 31;
            zB = ZB >> 31;
        }
        if (lane == 0) {
            g_cinfo[c] = zA | (zB << 1) | (cntA << 2) | (cntB << 17);
            g_gmask[c] = gmask;
        }
    }
}

// ============================================================================
// K2: per-batch scans + chunk sums -> g_entry, g_off
// ============================================================================
__global__ void __launch_bounds__(256)
k2_scan(const float* __restrict__ x0) {
    __shared__ float    s_e0s[(NTUM + 1) * 3];
    __shared__ unsigned s_entry[NCHUNK];
    __shared__ float    s_sx[NCHUNK], s_sy[NCHUNK], s_sz[NCHUNK];

    const int b    = blockIdx.x;
    const int tid  = threadIdx.x;
    const int w    = tid >> 5;
    const int lane = tid & 31;
    const unsigned FULL = 0xffffffffu;
    const unsigned lemask = FULL >> (31 - lane);
    const int cbase = b * NCHUNK;

    for (int i = tid; i < (NTUM + 1) * 3; i += 256)
        s_e0s[i] = g_e0s[b * (NTUM + 1) * 3 + i];

    // scan A (warp 0): chunk entry (z, C)
    if (w == 0) {
        unsigned m = 1u;
        int ck0 = lane * 4;
        unsigned mloc[4];
#pragma unroll
        for (int j = 0; j < 4; ++j) {
            int ck = ck0 + j;
            mloc[j] = (ck < NCHUNK) ? g_cinfo[cbase + ck] : 1u;
            m = composeMap(m, mloc[j]);
        }
#pragma unroll
        for (int k = 1; k < 32; k <<= 1) {
            unsigned mu = __shfl_up_sync(FULL, m, k);
            unsigned mc = composeMap(mu, m);
            if (lane >= k) m = mc;
        }
        unsigned ex = __shfl_up_sync(FULL, m, 1);
        if (lane == 0) ex = 1u;
        unsigned z = ex & 1u;
        unsigned C = (ex >> 2) & 0x7FFFu;
#pragma unroll
        for (int j = 0; j < 4; ++j) {
            int ck = ck0 + j;
            if (ck < NCHUNK) {
                unsigned e = z | (C << 1);
                s_entry[ck] = e;
                g_entry[cbase + ck] = e;
                unsigned mm = mloc[j];
                C += z ? ((mm >> 2) & 0x7FFFu) : ((mm >> 17) & 0x7FFFu);
                z = z ? (mm & 1u) : ((mm >> 1) & 1u);
            }
        }
    }
    __syncthreads();

    // chunk sums: warp w handles [w*16, min(w*16+16,125))
    int cs = w * 16;
    int ce = cs + 16 > NCHUNK ? NCHUNK : cs + 16;
    for (int ck = cs; ck < ce; ++ck) {
        unsigned e = s_entry[ck];
        unsigned z = e & 1u;
        int Cin = (int)(e >> 1);
        unsigned gm = g_gmask[cbase + ck];
        if (gm == 0x1Fu) {
            if (lane == 0) {
                float spd = z ? 1e-3f : 5e-3f;
                int idx = clipIdx(Cin);
                s_sx[ck] = CS * spd * s_e0s[idx * 3 + 0];
                s_sy[ck] = CS * spd * s_e0s[idx * 3 + 1];
                s_sz[ck] = CS * spd * s_e0s[idx * 3 + 2];
            }
            continue;
        }
        int sofar = 0;
        float ax = 0.f, ay = 0.f, az = 0.f;
        float ux = 0.f, uy = 0.f, uz = 0.f;
#pragma unroll
        for (int g = 0; g < NGRP; ++g) {
            if ((gm >> g) & 1u) {
                float spd = z ? 1e-3f : 5e-3f;
                int idx = clipIdx(Cin + sofar);
                ux += 32.f * spd * s_e0s[idx * 3 + 0];
                uy += 32.f * spd * s_e0s[idx * 3 + 1];
                uz += 32.f * spd * s_e0s[idx * 3 + 2];
                continue;
            }
            const unsigned* p = &g_ball[((cbase + ck) * NGRP + g) * 3];
            unsigned wA1 = p[0], wA2 = p[1], wB0 = p[2];
            unsigned Z = affineZ(wA1, wA2, wB0, z);
            unsigned Zp = (Z << 1) | z;
            unsigned S2 = Zp & wA2;
            unsigned S1 = (Zp & wA1) | (~Zp & ~wB0);
            if (ck == 0 && g == 0) S2 &= ~1u;
            int c = Cin + sofar + __popc(S2 & lemask);
            sofar += __popc(S2);
            z = Z >> 31;
            bool tum = (S2 >> lane) & 1u;
            if (ck == 0 && g == 0 && lane == 0) {
                ax += x0[b * 3 + 0]; ay += x0[b * 3 + 1]; az += x0[b * 3 + 2];
            } else if (!tum) {
                float spd = ((S1 >> lane) & 1u) ? 5e-3f : 1e-3f;
                int idx = clipIdx(c);
                ax += spd * s_e0s[idx * 3 + 0];
                ay += spd * s_e0s[idx * 3 + 1];
                az += spd * s_e0s[idx * 3 + 2];
            }
        }
#pragma unroll
        for (int o = 16; o; o >>= 1) {
            ax += __shfl_xor_sync(FULL, ax, o);
            ay += __shfl_xor_sync(FULL, ay, o);
            az += __shfl_xor_sync(FULL, az, o);
        }
        if (lane == 0) { s_sx[ck] = ux + ax; s_sy[ck] = uy + ay; s_sz[ck] = uz + az; }
    }
    __syncthreads();

    // offset scan (warp 0): exclusive prefix of chunk sums
    if (w == 0) {
        int ck0 = lane * 4;
        float lx[4], ly[4], lz[4];
        float tx = 0.f, ty = 0.f, tz = 0.f;
#pragma unroll
        for (int j = 0; j < 4; ++j) {
            int ck = ck0 + j;
            lx[j] = tx; ly[j] = ty; lz[j] = tz;
            if (ck < NCHUNK) { tx += s_sx[ck]; ty += s_sy[ck]; tz += s_sz[ck]; }
        }
        float ix = tx, iy = ty, iz = tz;
#pragma unroll
        for (int k = 1; k < 32; k <<= 1) {
            float sx = __shfl_up_sync(FULL, ix, k);
            float sy = __shfl_up_sync(FULL, iy, k);
            float sz = __shfl_up_sync(FULL, iz, k);
            if (lane >= k) { ix += sx; iy += sy; iz += sz; }
        }
        float bx = __shfl_up_sync(FULL, ix, 1);
        float by = __shfl_up_sync(FULL, iy, 1);
        float bz = __shfl_up_sync(FULL, iz, 1);
        if (lane == 0) { bx = by = bz = 0.f; }
#pragma unroll
        for (int j = 0; j < 4; ++j) {
            int ck = ck0 + j;
            if (ck < NCHUNK) {
                g_off[(cbase + ck) * 3 + 0] = bx + lx[j];
                g_off[(cbase + ck) * 3 + 1] = by + ly[j];
                g_off[(cbase + ck) * 3 + 2] = bz + lz[j];
            }
        }
    }
}

// ============================================================================
// K3: final recompute + staged coalesced write
// ============================================================================
__global__ void __launch_bounds__(256)
k3_write(const float* __restrict__ x0, float* __restrict__ out) {
    __shared__ float s_e0s[(NTUM + 1) * 3];
    __shared__ __align__(16) float s_stage[8][CS * 3];

    const int b    = blockIdx.x >> 2;
    const int seg  = blockIdx.x & 3;
    const int tid  = threadIdx.x;
    const int w    = tid >> 5;
    const int lane = tid & 31;
    const unsigned FULL = 0xffffffffu;
    const unsigned lemask = FULL >> (31 - lane);
    const int cbase = b * NCHUNK;

    for (int i = tid; i < (NTUM + 1) * 3; i += 256)
        s_e0s[i] = g_e0s[b * (NTUM + 1) * 3 + i];
    __syncthreads();

    const int ce = (seg == 3) ? NCHUNK : (seg * 32 + 32);
    float* st = &s_stage[w][0];
#pragma unroll
    for (int j = 0; j < 4; ++j) {
        int ck = seg * 32 + w * 4 + j;
        if (ck >= ce) break;
        unsigned e = g_entry[cbase + ck];
        unsigned z = e & 1u;
        int Cin = (int)(e >> 1);
        float cx = g_off[(cbase + ck) * 3 + 0];
        float cy = g_off[(cbase + ck) * 3 + 1];
        float cz = g_off[(cbase + ck) * 3 + 2];
        unsigned gm = g_gmask[cbase + ck];
        if (gm == 0x1Fu) {                 // whole-chunk fast: linear ramp
            float spd = z ? 1e-3f : 5e-3f;
            int idx = clipIdx(Cin);
            float vx = spd * s_e0s[idx * 3 + 0];
            float vy = spd * s_e0s[idx * 3 + 1];
            float vz = spd * s_e0s[idx * 3 + 2];
#pragma unroll
            for (int g = 0; g < NGRP; ++g) {
                float t = (float)(g * 32 + lane + 1);
                int o = (g * 32 + lane) * 3;
                st[o + 0] = fmaf(t, vx, cx);
                st[o + 1] = fmaf(t, vy, cy);
                st[o + 2] = fmaf(t, vz, cz);
            }
        } else {
            int sofar = 0;
#pragma unroll
            for (int g = 0; g < NGRP; ++g) {
                int o = (g * 32 + lane) * 3;
                if ((gm >> g) & 1u) {      // fast group: ramp
                    float spd = z ? 1e-3f : 5e-3f;
                    int idx = clipIdx(Cin + sofar);
                    float vx = spd * s_e0s[idx * 3 + 0];
                    float vy = spd * s_e0s[idx * 3 + 1];
                    float vz = spd * s_e0s[idx * 3 + 2];
                    float t = (float)(lane + 1);
                    st[o + 0] = fmaf(t, vx, cx);
                    st[o + 1] = fmaf(t, vy, cy);
                    st[o + 2] = fmaf(t, vz, cz);
                    cx = fmaf(32.f, vx, cx);
                    cy = fmaf(32.f, vy, cy);
                    cz = fmaf(32.f, vz, cz);
                    continue;
                }
                const unsigned* p = &g_ball[((cbase + ck) * NGRP + g) * 3];
                unsigned wA1 = p[0], wA2 = p[1], wB0 = p[2];
                unsigned Z = affineZ(wA1, wA2, wB0, z);
                unsigned Zp = (Z << 1) | z;
                unsigned S2 = Zp & wA2;
                unsigned S1 = (Zp & wA1) | (~Zp & ~wB0);
                if (ck == 0 && g == 0) S2 &= ~1u;
                int c = Cin + sofar + __popc(S2 & lemask);
                sofar += __popc(S2);
                z = Z >> 31;
                float vx, vy, vz;
                bool tum = (S2 >> lane) & 1u;
                if (ck == 0 && g == 0 && lane == 0) {
                    vx = x0[b * 3 + 0]; vy = x0[b * 3 + 1]; vz = x0[b * 3 + 2];
                } else if (tum) {
                    vx = vy = vz = 0.f;
                } else {
                    float spd = ((S1 >> lane) & 1u) ? 5e-3f : 1e-3f;
                    int idx = clipIdx(c);
                    vx = spd * s_e0s[idx * 3 + 0];
                    vy = spd * s_e0s[idx * 3 + 1];
                    vz = spd * s_e0s[idx * 3 + 2];
                }
#pragma unroll
                for (int oo = 1; oo < 32; oo <<= 1) {
                    float txu = __shfl_up_sync(FULL, vx, oo);
                    float tyu = __shfl_up_sync(FULL, vy, oo);
                    float tzu = __shfl_up_sync(FULL, vz, oo);
                    if (lane >= oo) { vx += txu; vy += tyu; vz += tzu; }
                }
                st[o + 0] = cx + vx;
                st[o + 1] = cy + vy;
                st[o + 2] = cz + vz;
                cx += __shfl_sync(FULL, vx, 31);
                cy += __shfl_sync(FULL, vy, 31);
                cz += __shfl_sync(FULL, vz, 31);
            }
        }
        __syncwarp();
        float4* o4 = reinterpret_cast<float4*>(out + (size_t)(b * NSTEPS + ck * CS) * 3);
        const float4* s4 = reinterpret_cast<const float4*>(st);
#pragma unroll
        for (int i = 0; i < 4; ++i) {
            int idx4 = i * 32 + lane;
            if (idx4 < 120) o4[idx4] = s4[idx4];
        }
        __syncwarp();
    }
}

// ---------------- launch ----------------------------------------------------
extern "C" void kernel_launch(void* const* d_in, const int* in_sizes, int n_in,
                              void* d_out, int out_size) {
    const float* x0 = (const float*)d_in[0];
    const float* v0 = (const float*)d_in[1];
    const float* v1 = (const float*)d_in[2];
    const float* r0 = (const float*)d_in[3];
    const float* r1 = (const float*)d_in[4];
    const float* up = (const float*)d_in[5];
    const float* un = (const float*)d_in[6];
    float* X = (float*)d_out;

    k1_ballots<<<K1_WORK_BLOCKS + K1_FRAME_BLOCKS, 256>>>(r0, r1, v0, v1, up, un);
    k2_scan<<<BATCH, 256>>>(x0);
    k3_write<<<K3_BLOCKS, 256>>>(x0, X);
}